// round 13
// baseline (speedup 1.0000x reference)
#include <cuda_runtime.h>
#include <cstdint>
#include <math.h>

#define BATCH 32
#define HEADS 32
#define KVHEADS 8
#define DIM 128
#define KCTX 4096
#define HSZ 4096
#define GRP 4
#define NSPLIT 16
#define KSG 32                     // gemm k-splits
#define QK_SCALE 0.08838834764831845f
#define M_FIX 16.0f                // fixed softmax shift (scale-invariant)

// ------------------------------ scratch (no allocs allowed) ------------------
__device__ float g_q[BATCH * HSZ];                              // 512 KB
__device__ float g_attn[BATCH * HSZ];                           // tf32-rounded attn
__device__ float g_hs_hi[BATCH * HSZ];                          // hs tf32 hi plane
__device__ float g_hs_lo[BATCH * HSZ];                          // hs tf32 lo plane
__device__ float g_gpart[KSG * BATCH * HSZ];                    // 16 MB (gemm split-K partials)
__device__ float g_pacc[BATCH * KVHEADS * NSPLIT * GRP * DIM];  // 8 MB (attn partials)
__device__ float g_pl[BATCH * KVHEADS * NSPLIT * GRP];

// ------------------------------ helpers -------------------------------------
__device__ __forceinline__ unsigned f2tf(float x) {
    unsigned r;
    asm("cvt.rna.tf32.f32 %0, %1;" : "=r"(r) : "f"(x));
    return r;
}

__device__ __forceinline__ void cpasync16(void* smem_dst, const void* gsrc) {
    unsigned d = (unsigned)__cvta_generic_to_shared(smem_dst);
    asm volatile("cp.async.cg.shared.global [%0], [%1], 16;"
                 :: "r"(d), "l"(gsrc) : "memory");
}

// m16n8k8 tf32 MMA: A frag {a0..a3}, B frag {b0,b1}, fp32 accum in-place.
#define MMA8(C, Ar, B0, B1)                                                    \
    asm volatile(                                                              \
        "mma.sync.aligned.m16n8k8.row.col.f32.tf32.tf32.f32 "                  \
        "{%0,%1,%2,%3},{%4,%5,%6,%7},{%8,%9},{%0,%1,%2,%3};"                   \
        : "+f"((C)[0]), "+f"((C)[1]), "+f"((C)[2]), "+f"((C)[3])               \
        : "r"((Ar)[0]), "r"((Ar)[1]), "r"((Ar)[2]), "r"((Ar)[3]),              \
          "r"(B0), "r"(B1))

// ---------------- split hs into tf32 hi/lo planes (once per launch) ---------
// 131072 elements, float4 per thread. grid 128, block 256.
__global__ void split_hs(const float* __restrict__ hs) {
    int i = (blockIdx.x * blockDim.x + threadIdx.x) * 4;
    float4 x = *(const float4*)(hs + i);
    float4 h, lo;
    h.x = __uint_as_float(f2tf(x.x)); lo.x = __uint_as_float(f2tf(x.x - h.x));
    h.y = __uint_as_float(f2tf(x.y)); lo.y = __uint_as_float(f2tf(x.y - h.y));
    h.z = __uint_as_float(f2tf(x.z)); lo.z = __uint_as_float(f2tf(x.z - h.z));
    h.w = __uint_as_float(f2tf(x.w)); lo.w = __uint_as_float(f2tf(x.w - h.w));
    *(float4*)(g_hs_hi + i) = h;
    *(float4*)(g_hs_lo + i) = lo;
}

// ------------------------------ GEMM (3xTF32, pre-split A, k8) ---------------
// out[b,n] = sum_k A[b,k] * W[n,k]. A given as tf32 hi/lo planes.
// Grid (32 n-tiles of 128, KSG k-splits), 128 thr (4 warps), warp = m32 x n32.
// D = Ah*Bh + Al*Bh + Ah*Bl (fp32 accum) ~ fp32. Used for wq (softmax-critical).
__global__ __launch_bounds__(128) void gemm_tf32(const float* __restrict__ W) {
    __shared__ float Ah_s[2][32][36];
    __shared__ float Al_s[2][32][36];
    __shared__ float Ws[2][128][36];
    const int tid = threadIdx.x;
    const int ng = tid >> 5;           // n32 group (0..3)
    const int lane = tid & 31;
    const int groupID = lane >> 2;
    const int tig = lane & 3;
    const int n0 = blockIdx.x * 128;
    const int ks = blockIdx.y;
    const int kbeg = ks * (HSZ / KSG); // 128-wide k chunk, 4 stages of 32

    float c[2][4][4] = {};             // [m-half][n8-tile][c0..c3]

#define LOAD_STAGE_Q(s, kb)                                                    \
    do {                                                                       \
        _Pragma("unroll")                                                      \
        for (int r_ = 0; r_ < 2; r_++) {                                       \
            int idx_ = tid + 128 * r_;                                         \
            int ar_ = idx_ >> 3, ak_ = (idx_ & 7) * 4;                         \
            size_t go_ = (size_t)ar_ * HSZ + (kb) + ak_;                       \
            cpasync16(&Ah_s[s][ar_][ak_], g_hs_hi + go_);                      \
            cpasync16(&Al_s[s][ar_][ak_], g_hs_lo + go_);                      \
        }                                                                      \
        _Pragma("unroll")                                                      \
        for (int r_ = 0; r_ < 8; r_++) {                                       \
            int idx_ = tid + 128 * r_;                                         \
            int wr_ = idx_ >> 3, wk_ = (idx_ & 7) * 4;                         \
            cpasync16(&Ws[s][wr_][wk_],                                        \
                      W + (size_t)(n0 + wr_) * HSZ + (kb) + wk_);              \
        }                                                                      \
        asm volatile("cp.async.commit_group;" ::: "memory");                   \
    } while (0)

    LOAD_STAGE_Q(0, kbeg);
    #pragma unroll 1
    for (int i = 0; i < 4; i++) {
        const int s = i & 1;
        if (i < 3) {
            LOAD_STAGE_Q(s ^ 1, kbeg + (i + 1) * 32);
            asm volatile("cp.async.wait_group 1;" ::: "memory");
        } else {
            asm volatile("cp.async.wait_group 0;" ::: "memory");
        }
        __syncthreads();

        #pragma unroll
        for (int k8 = 0; k8 < 4; k8++) {
            const int k = k8 * 8 + tig;
            unsigned ah[2][4], al[2][4];
            #pragma unroll
            for (int mh = 0; mh < 2; mh++) {
                #pragma unroll
                for (int t = 0; t < 4; t++) {
                    int row = mh * 16 + groupID + (t & 1) * 8;
                    int col = k + (t >> 1) * 4;
                    ah[mh][t] = __float_as_uint(Ah_s[s][row][col]);
                    al[mh][t] = __float_as_uint(Al_s[s][row][col]);
                }
            }
            #pragma unroll
            for (int nt = 0; nt < 4; nt++) {
                int n = ng * 32 + nt * 8 + groupID;
                float b0f = Ws[s][n][k];
                float b1f = Ws[s][n][k + 4];
                unsigned bh0 = f2tf(b0f), bh1 = f2tf(b1f);
                unsigned bl0 = f2tf(b0f - __uint_as_float(bh0));
                unsigned bl1 = f2tf(b1f - __uint_as_float(bh1));
                #pragma unroll
                for (int mh = 0; mh < 2; mh++) {
                    MMA8(c[mh][nt], ah[mh], bh0, bh1);
                    MMA8(c[mh][nt], al[mh], bh0, bh1);
                    MMA8(c[mh][nt], ah[mh], bl0, bl1);
                }
            }
        }
        __syncthreads();
    }
#undef LOAD_STAGE_Q

    float* outp = g_gpart + (size_t)ks * (BATCH * HSZ);
    #pragma unroll
    for (int mh = 0; mh < 2; mh++) {
        const int m = mh * 16 + groupID;
        #pragma unroll
        for (int nt = 0; nt < 4; nt++) {
            int n = n0 + ng * 32 + nt * 8 + 2 * tig;
            *(float2*)&outp[(size_t)m * HSZ + n] =
                make_float2(c[mh][nt][0], c[mh][nt][1]);
            *(float2*)&outp[(size_t)(m + 8) * HSZ + n] =
                make_float2(c[mh][nt][2], c[mh][nt][3]);
        }
    }
}

// ------------------------------ GEMM (1xTF32, fast, k8) ----------------------
// A (g_attn) is already tf32-rounded by attn_reduce: pure LDS + reinterpret.
// Used for wo only (pure linear map; ~2e-4 rel error unamplified).
__global__ __launch_bounds__(128) void gemm_tf32_fast(const float* __restrict__ A,
                                                      const float* __restrict__ W) {
    __shared__ float As[2][32][36];
    __shared__ float Ws[2][128][36];
    const int tid = threadIdx.x;
    const int ng = tid >> 5;
    const int lane = tid & 31;
    const int groupID = lane >> 2;
    const int tig = lane & 3;
    const int n0 = blockIdx.x * 128;
    const int ks = blockIdx.y;
    const int kbeg = ks * (HSZ / KSG);

    float c[2][4][4] = {};

#define LOAD_STAGE_F(s, kb)                                                    \
    do {                                                                       \
        _Pragma("unroll")                                                      \
        for (int r_ = 0; r_ < 2; r_++) {                                       \
            int idx_ = tid + 128 * r_;                                         \
            int ar_ = idx_ >> 3, ak_ = (idx_ & 7) * 4;                         \
            cpasync16(&As[s][ar_][ak_], A + (size_t)ar_ * HSZ + (kb) + ak_);   \
        }                                                                      \
        _Pragma("unroll")                                                      \
        for (int r_ = 0; r_ < 8; r_++) {                                       \
            int idx_ = tid + 128 * r_;                                         \
            int wr_ = idx_ >> 3, wk_ = (idx_ & 7) * 4;                         \
            cpasync16(&Ws[s][wr_][wk_],                                        \
                      W + (size_t)(n0 + wr_) * HSZ + (kb) + wk_);              \
        }                                                                      \
        asm volatile("cp.async.commit_group;" ::: "memory");                   \
    } while (0)

    LOAD_STAGE_F(0, kbeg);
    #pragma unroll 1
    for (int i = 0; i < 4; i++) {
        const int s = i & 1;
        if (i < 3) {
            LOAD_STAGE_F(s ^ 1, kbeg + (i + 1) * 32);
            asm volatile("cp.async.wait_group 1;" ::: "memory");
        } else {
            asm volatile("cp.async.wait_group 0;" ::: "memory");
        }
        __syncthreads();

        #pragma unroll
        for (int k8 = 0; k8 < 4; k8++) {
            const int k = k8 * 8 + tig;
            unsigned ah[2][4];
            #pragma unroll
            for (int mh = 0; mh < 2; mh++) {
                #pragma unroll
                for (int t = 0; t < 4; t++) {
                    int row = mh * 16 + groupID + (t & 1) * 8;
                    int col = k + (t >> 1) * 4;
                    ah[mh][t] = __float_as_uint(As[s][row][col]);
                }
            }
            #pragma unroll
            for (int nt = 0; nt < 4; nt++) {
                int n = ng * 32 + nt * 8 + groupID;
                unsigned bh0 = f2tf(Ws[s][n][k]);
                unsigned bh1 = f2tf(Ws[s][n][k + 4]);
                MMA8(c[0][nt], ah[0], bh0, bh1);
                MMA8(c[1][nt], ah[1], bh0, bh1);
            }
        }
        __syncthreads();
    }
#undef LOAD_STAGE_F

    float* outp = g_gpart + (size_t)ks * (BATCH * HSZ);
    #pragma unroll
    for (int mh = 0; mh < 2; mh++) {
        const int m = mh * 16 + groupID;
        #pragma unroll
        for (int nt = 0; nt < 4; nt++) {
            int n = n0 + ng * 32 + nt * 8 + 2 * tig;
            *(float2*)&outp[(size_t)m * HSZ + n] =
                make_float2(c[mh][nt][0], c[mh][nt][1]);
            *(float2*)&outp[(size_t)(m + 8) * HSZ + n] =
                make_float2(c[mh][nt][2], c[mh][nt][3]);
        }
    }
}

// sum the KSG split-K partials into dst, float4-vectorized. grid 128, block 256.
__global__ void ksum_part(float* __restrict__ dst) {
    int i = (blockIdx.x * blockDim.x + threadIdx.x) * 4;
    float4 s = make_float4(0.f, 0.f, 0.f, 0.f);
    #pragma unroll
    for (int p = 0; p < KSG; p++) {
        float4 t = *(const float4*)(g_gpart + (size_t)p * (BATCH * HSZ) + i);
        s.x += t.x; s.y += t.y; s.z += t.z; s.w += t.w;
    }
    *(float4*)(dst + i) = s;
}

// ------------------ fused split-K sum + RoPE -> g_q --------------------------
// grid = B*H (1024), block = 64 (one thread per rotation pair).
__global__ void ksum_rope(const int* __restrict__ positions) {
    const int bh = blockIdx.x;
    const int b = bh >> 5;
    const int j = threadIdx.x;           // 0..63
    const size_t base = (size_t)bh << 7;

    float q1 = 0.f, q2 = 0.f;
    #pragma unroll
    for (int p = 0; p < KSG; p++) {
        const float* gp = g_gpart + (size_t)p * (BATCH * HSZ) + base;
        q1 += gp[j];
        q2 += gp[j + 64];
    }

    double inv = exp(-(double)j * (13.815510557964274 / 64.0));
    double ang = (double)positions[b] * inv;
    double sd, cd;
    sincos(ang, &sd, &cd);
    float c = (float)cd, s = (float)sd;
    float* qp = g_q + base;
    qp[j]      = q1 * c - q2 * s;
    qp[j + 64] = q2 * c + q1 * s;
}

// ------------------------------ attention ----------------------------------
// grid = B*KVH*NSPLIT (4096), block 128 (4 warps). Full warp per key.
// cp.async depth-4 smem ring per warp. q in registers. Fixed-shift softmax.
__global__ __launch_bounds__(128, 8) void attn_kernel(const float* __restrict__ kc,
                                                      const float* __restrict__ vc,
                                                      const int* __restrict__ clens) {
    const int blk = blockIdx.x;
    const int split = blk & 15;
    const int kvh = (blk >> 4) & 7;
    const int b = blk >> 7;
    const int tid = threadIdx.x;
    const int wid = tid >> 5;
    const int lane = tid & 31;

    __shared__ float4 ring[4][4][64];   // [warp][stage][K:0-31 | V:32-63]  16 KB
    __shared__ float sl[4][GRP];
    __shared__ float sacc[4][GRP][DIM]; // 8 KB

    float4 q[GRP];
    {
        const float* qg = g_q + ((size_t)(b * HEADS + kvh * GRP) << 7) + lane * 4;
        #pragma unroll
        for (int g = 0; g < GRP; g++) {
            float4 t = *(const float4*)(qg + g * DIM);
            q[g].x = t.x * QK_SCALE; q[g].y = t.y * QK_SCALE;
            q[g].z = t.z * QK_SCALE; q[g].w = t.w * QK_SCALE;
        }
    }

    const int ctx = clens[b];
    const size_t rs = (size_t)KVHEADS * DIM; // 1024 floats per key index
    const float* kp = kc + (size_t)b * KCTX * rs + (size_t)kvh * DIM + lane * 4;
    const float* vp = vc + (size_t)b * KCTX * rs + (size_t)kvh * DIM + lane * 4;

    float l[4] = {0.f, 0.f, 0.f, 0.f};
    float4 acc[4];
    #pragma unroll
    for (int g = 0; g < 4; g++) acc[g] = make_float4(0.f, 0.f, 0.f, 0.f);

    const unsigned rb =
        (unsigned)__cvta_generic_to_shared(&ring[wid][0][0]) + lane * 16u;

    const int j0 = split + 16 * wid;   // this warp's first key; stride 64
    const int gsel = lane >> 3;        // which head this 8-lane group reduces
    const int lsub = lane & 7;

    #pragma unroll
    for (int s = 0; s < 3; s++) {
        int jc = min(j0 + 64 * s, ctx - 1);
        unsigned dst = rb + s * 1024u;
        asm volatile("cp.async.cg.shared.global [%0], [%1], 16;"
                     :: "r"(dst), "l"(kp + (size_t)jc * rs) : "memory");
        asm volatile("cp.async.cg.shared.global [%0], [%1], 16;"
                     :: "r"(dst + 512u), "l"(vp + (size_t)jc * rs) : "memory");
        asm volatile("cp.async.commit_group;" ::: "memory");
    }

    int j = j0;
    int it = 0;
    while (j < ctx) {
        asm volatile("cp.async.wait_group 2;" ::: "memory");
        const int cur = it & 3;
        float4 kv = ring[wid][cur][lane];
        float4 vv = ring[wid][cur][32 + lane];

        {
            int jc = min(j + 192, ctx - 1);
            unsigned dst = rb + ((unsigned)((it + 3) & 3)) * 1024u;
            asm volatile("cp.async.cg.shared.global [%0], [%1], 16;"
                         :: "r"(dst), "l"(kp + (size_t)jc * rs) : "memory");
            asm volatile("cp.async.cg.shared.global [%0], [%1], 16;"
                         :: "r"(dst + 512u), "l"(vp + (size_t)jc * rs) : "memory");
            asm volatile("cp.async.commit_group;" ::: "memory");
        }

        float sv[4];
        #pragma unroll
        for (int g = 0; g < 4; g++)
            sv[g] = fmaf(q[g].x, kv.x, fmaf(q[g].y, kv.y,
                     fmaf(q[g].z, kv.z, q[g].w * kv.w)));

        #pragma unroll
        for (int off = 16; off >= 8; off >>= 1) {
            sv[0] += __shfl_xor_sync(0xffffffffu, sv[0], off);
            sv[1] += __shfl_xor_sync(0xffffffffu, sv[1], off);
            sv[2] += __shfl_xor_sync(0xffffffffu, sv[2], off);
            sv[3] += __shfl_xor_sync(0xffffffffu, sv[3], off);
        }
        float v = (gsel == 0) ? sv[0] : (gsel == 1) ? sv[1]
                : (gsel == 2) ? sv[2] : sv[3];
        v += __shfl_xor_sync(0xffffffffu, v, 4);
        v += __shfl_xor_sync(0xffffffffu, v, 2);
        v += __shfl_xor_sync(0xffffffffu, v, 1);
        float pown = __expf(v - M_FIX);
        float p[4];
        #pragma unroll
        for (int g = 0; g < 4; g++)
            p[g] = __shfl_sync(0xffffffffu, pown, (g << 3) | lsub);

        #pragma unroll
        for (int g = 0; g < 4; g++) {
            l[g] += p[g];
            acc[g].x = fmaf(p[g], vv.x, acc[g].x);
            acc[g].y = fmaf(p[g], vv.y, acc[g].y);
            acc[g].z = fmaf(p[g], vv.z, acc[g].z);
            acc[g].w = fmaf(p[g], vv.w, acc[g].w);
        }
        j += 64;
        it++;
    }

    if (lane == 0) {
        #pragma unroll
        for (int g = 0; g < 4; g++) sl[wid][g] = l[g];
    }
    #pragma unroll
    for (int g = 0; g < 4; g++)
        *(float4*)(&sacc[wid][g][lane * 4]) = acc[g];
    __syncthreads();

    const int g = tid >> 5;
    const int l32 = tid & 31;
    float L = 0.f;
    float4 V = make_float4(0.f, 0.f, 0.f, 0.f);
    #pragma unroll
    for (int w = 0; w < 4; w++) {
        L += sl[w][g];
        float4 a = *(const float4*)(&sacc[w][g][l32 * 4]);
        V.x += a.x; V.y += a.y; V.z += a.z; V.w += a.w;
    }
    const size_t pb = (size_t)(blk * GRP + g) * DIM;
    *(float4*)&g_pacc[pb + l32 * 4] = V;
    if (l32 == 0) g_pl[blk * GRP + g] = L;
}

// combine NSPLIT partials -> g_attn (tf32-rounded). grid = B*KVH*G (1024), block 32.
// One warp per (b,kvh,g); float4 per lane; 16 outstanding float4 loads (MLP).
__global__ void attn_reduce() {
    const int idx = blockIdx.x;
    const int g = idx & 3;
    const int kvh = (idx >> 2) & 7;
    const int b = idx >> 5;
    const int lane = threadIdx.x;        // 0..31, owns dims [4*lane, 4*lane+4)
    const int base = ((b * KVHEADS + kvh) * NSPLIT) * GRP + g;

    float L = 0.f;
    float4 a = make_float4(0.f, 0.f, 0.f, 0.f);
    #pragma unroll
    for (int s = 0; s < NSPLIT; s++) {
        L += g_pl[base + s * GRP];
        float4 t = *(const float4*)(g_pacc + (size_t)(base + s * GRP) * DIM + lane * 4);
        a.x += t.x; a.y += t.y; a.z += t.z; a.w += t.w;
    }
    float inv = 1.f / L;
    // round to tf32 here (identical bits to what gemm_fast's f2tf produced)
    float4 o;
    o.x = __uint_as_float(f2tf(a.x * inv));
    o.y = __uint_as_float(f2tf(a.y * inv));
    o.z = __uint_as_float(f2tf(a.z * inv));
    o.w = __uint_as_float(f2tf(a.w * inv));
    *(float4*)(g_attn + (((size_t)(b * HEADS + kvh * GRP + g)) << 7) + lane * 4) = o;
}

// ------------------------------ launch --------------------------------------
extern "C" void kernel_launch(void* const* d_in, const int* in_sizes, int n_in,
                              void* d_out, int out_size) {
    const float* hs = (const float*)d_in[0];
    const int* pos = (const int*)d_in[1];
    const float* kc = (const float*)d_in[2];
    const float* vc = (const float*)d_in[3];
    const int* cl = (const int*)d_in[4];
    const float* wq = (const float*)d_in[5];
    const float* wo = (const float*)d_in[6];
    float* out = (float*)d_out;

    float* abuf = nullptr;
    cudaGetSymbolAddress((void**)&abuf, g_attn);

    // split hs into tf32 hi/lo planes
    split_hs<<<128, 256>>>(hs);
    // q = rope(hs @ wq.T)   (3xTF32 k8, pre-split A; fused sum+rope)
    gemm_tf32<<<dim3(32, KSG), 128>>>(wq);
    ksum_rope<<<1024, 64>>>(pos);
    // flash-decode attention, strided split over K
    attn_kernel<<<BATCH * KVHEADS * NSPLIT, 128>>>(kc, vc, cl);
    attn_reduce<<<BATCH * KVHEADS * GRP, 32>>>();
    // out = attn @ wo.T  (1xTF32 k8: linear on output, error unamplified)
    gemm_tf32_fast<<<dim3(32, KSG), 128>>>(abuf, wo);
    ksum_part<<<128, 256>>>(out);
}